// round 17
// baseline (speedup 1.0000x reference)
#include <cuda_runtime.h>

#define Bq  256
#define Tq  2000
#define Fq  80
#define Hq  64
#define G3q 192
#define Oq  29

// Precomputed layer-0 input projection: gx0[b][t][g] (393 MB static device scratch)
__device__ float g_gx0[(size_t)Bq * Tq * G3q];

// MUFU.TANH (sm_75+)
__device__ __forceinline__ float tanha(float x) {
    float y;
    asm("tanh.approx.f32 %0, %1;" : "=f"(y) : "f"(x));
    return y;
}
__device__ __forceinline__ float siga(float x) {
    return fmaf(tanha(0.5f * x), 0.5f, 0.5f);
}

// Blackwell packed f32x2 FMA (PTX-only; ptxas never auto-fuses)
__device__ __forceinline__ float2 ffma2(float2 a, float2 b, float2 c) {
    float2 d;
    asm("fma.rn.f32x2 %0, %1, %2, %3;"
        : "=l"(*reinterpret_cast<unsigned long long*>(&d))
        : "l"(*reinterpret_cast<unsigned long long*>(&a)),
          "l"(*reinterpret_cast<unsigned long long*>(&b)),
          "l"(*reinterpret_cast<unsigned long long*>(&c)));
    return d;
}

// ---------------------------------------------------------------------------
// Kernel 1: gx0 = x @ W_ih0^T + b_ih0  (R8 proven config: grid 256, 2 blk/SM,
// register weight rows, 4 timesteps in flight, natural-layout x staging).
// ---------------------------------------------------------------------------
__global__ __launch_bounds__(192, 2) void gx0_kernel(
    const float* __restrict__ x,
    const float* __restrict__ W_ih0,
    const float* __restrict__ b_ih0)
{
    __shared__ float xs[40 * Fq];          // 12.8 KB, [t][f] natural layout

    const int g = threadIdx.x;             // gate 0..191
    const int b = blockIdx.x;              // batch

    float2 wv[40];
    {
        const float2* Wp = reinterpret_cast<const float2*>(W_ih0 + g * Fq);
        #pragma unroll
        for (int k = 0; k < 40; ++k) wv[k] = Wp[k];
    }
    const float bias = b_ih0[g];

    const float4* xg = reinterpret_cast<const float4*>(x + (size_t)b * Tq * Fq);
    float* outp = g_gx0 + (size_t)b * Tq * G3q + g;

    for (int c = 0; c < 50; ++c) {
        const float4* src = xg + c * (40 * Fq / 4);
        #pragma unroll 1
        for (int i = g; i < 800; i += 192)
            reinterpret_cast<float4*>(xs)[i] = src[i];
        __syncthreads();

        #pragma unroll 1
        for (int tg = 0; tg < 10; ++tg) {
            const float4* x0 = reinterpret_cast<const float4*>(&xs[(tg * 4 + 0) * Fq]);
            const float4* x1 = reinterpret_cast<const float4*>(&xs[(tg * 4 + 1) * Fq]);
            const float4* x2 = reinterpret_cast<const float4*>(&xs[(tg * 4 + 2) * Fq]);
            const float4* x3 = reinterpret_cast<const float4*>(&xs[(tg * 4 + 3) * Fq]);
            float2 a0 = make_float2(bias, 0.0f);
            float2 a1 = make_float2(bias, 0.0f);
            float2 a2 = make_float2(bias, 0.0f);
            float2 a3 = make_float2(bias, 0.0f);
            #pragma unroll
            for (int k = 0; k < 20; ++k) {
                float2 wlo = wv[2 * k], whi = wv[2 * k + 1];
                float4 v0 = x0[k];
                a0 = ffma2(wlo, make_float2(v0.x, v0.y), a0);
                a0 = ffma2(whi, make_float2(v0.z, v0.w), a0);
                float4 v1 = x1[k];
                a1 = ffma2(wlo, make_float2(v1.x, v1.y), a1);
                a1 = ffma2(whi, make_float2(v1.z, v1.w), a1);
                float4 v2 = x2[k];
                a2 = ffma2(wlo, make_float2(v2.x, v2.y), a2);
                a2 = ffma2(whi, make_float2(v2.z, v2.w), a2);
                float4 v3 = x3[k];
                a3 = ffma2(wlo, make_float2(v3.x, v3.y), a3);
                a3 = ffma2(whi, make_float2(v3.z, v3.w), a3);
            }
            int tbase = c * 40 + tg * 4;
            outp[(size_t)(tbase + 0) * G3q] = a0.x + a0.y;
            outp[(size_t)(tbase + 1) * G3q] = a1.x + a1.y;
            outp[(size_t)(tbase + 2) * G3q] = a2.x + a2.y;
            outp[(size_t)(tbase + 3) * G3q] = a3.x + a3.y;
        }
        __syncthreads();
    }
}

// ---------------------------------------------------------------------------
// Kernel 2: fused 2-layer GRU + FC — ONE batch per block, 2 blocks/SM.
// Same split as R7 but single batch (weights halve to 48 regs/thread), so two
// independent barrier domains co-reside per SM and hide each other's tails.
//   tid   0..127: L0, j = tid>>1, seg = tid&1  (K half = hbuf quarter seg)
//   tid 128..383: L1, j = (tid-128)>>2, seg = (tid-128)&3 (concat quarter)
// Act on seg==0 lanes. Reduction: L0 xor1; L1 xor1 + xor2 (r/z sum across
// sides, n-dot exchanged).
// ---------------------------------------------------------------------------
__global__ __launch_bounds__(384, 2) void rnn_kernel(
    const float* __restrict__ h_in,
    const float* __restrict__ W_hh0, const float* __restrict__ b_hh0,
    const float* __restrict__ W_ih1, const float* __restrict__ W_hh1,
    const float* __restrict__ b_ih1, const float* __restrict__ b_hh1,
    const float* __restrict__ W_fc,  const float* __restrict__ b_fc,
    float* __restrict__ out, int write_hidden)
{
    // [parity][quarter of concat [h0;h1]][32 + 8 pad]
    __shared__ float hbuf[2][4][40];

    const int tid   = threadIdx.x;
    const int batch = blockIdx.x;
    const bool isL0 = tid < 128;
    int j, seg;
    if (isL0) { j = tid >> 1; seg = tid & 1; }
    else      { int t = tid - 128; j = t >> 2; seg = t & 3; }

    // --- weight windows (r,z,n) -> registers: 8 float4 per gate? no: 8 k for
    // L0 halves/L1 quarters = 8 float4 each gate => 24 float4 would be 96 regs.
    // Single batch uses SAME window size as R7 (32 floats = 8 float4 per gate).
    float4 wR[8], wZ[8], wN[8];
    {
        const float4* W;
        int k0;
        if (isL0)          { W = (const float4*)W_hh0; k0 = seg * 8; }
        else if (seg < 2)  { W = (const float4*)W_ih1; k0 = seg * 8; }
        else               { W = (const float4*)W_hh1; k0 = (seg - 2) * 8; }
        #pragma unroll
        for (int k = 0; k < 8; ++k) {
            wR[k] = W[(j      ) * 16 + k0 + k];
            wZ[k] = W[(64 + j ) * 16 + k0 + k];
            wN[k] = W[(128 + j) * 16 + k0 + k];
        }
    }
    float bR, bZ, bNi = 0.0f, bNh;
    if (isL0) {
        bR = b_hh0[j]; bZ = b_hh0[64 + j]; bNh = b_hh0[128 + j];
    } else {
        bR  = b_ih1[j] + b_hh1[j];
        bZ  = b_ih1[64 + j] + b_hh1[64 + j];
        bNi = b_ih1[128 + j]; bNh = b_hh1[128 + j];
    }

    // --- init: h0^0 -> parity0 q0/q1 ; h1^0 -> parity1 q2/q3 ---
    if (tid < 128) {
        if (tid < 64) {
            hbuf[0][tid >> 5][tid & 31] = h_in[batch * Hq + tid];
            hbuf[1][tid >> 5][tid & 31] = 0.0f;
        } else {
            int jj = tid - 64;
            hbuf[1][2 + (jj >> 5)][jj & 31] = h_in[Bq * Hq + batch * Hq + jj];
            hbuf[0][2 + (jj >> 5)][jj & 31] = 0.0f;
        }
    }
    __syncthreads();

    // gx stream (act lanes: seg==0)
    const float* gxp = g_gx0 + (size_t)batch * Tq * G3q;
    float gxR = 0.0f, gxZ = 0.0f, gxN = 0.0f;
    if (isL0 && seg == 0) { gxR = gxp[j]; gxZ = gxp[64 + j]; gxN = gxp[128 + j]; }

    float hprev = 0.0f;
    if (seg == 0) {
        hprev = isL0 ? h_in[batch * Hq + j] : h_in[Bq * Hq + batch * Hq + j];
    }

    for (int i = 0; i <= Tq; ++i) {
        const int p = i & 1;

        // prefetch next step's gx (hidden behind the whole step)
        float nR = 0.0f, nZ = 0.0f, nN = 0.0f;
        if (isL0 && seg == 0 && i + 1 < Tq) {
            const float* gq = gxp + (size_t)(i + 1) * G3q;
            nR = __ldg(gq + j); nZ = __ldg(gq + 64 + j); nN = __ldg(gq + 128 + j);
        }

        // --- partial dots over this thread's 32-float window (quarter seg) ---
        const float4* u4 = (const float4*)&hbuf[p][seg][0];
        float2 aR = {0,0}, aZ = {0,0}, aN = {0,0};
        #pragma unroll
        for (int k = 0; k < 8; ++k) {
            float4 u = u4[k];
            float2 ulo = make_float2(u.x, u.y), uhi = make_float2(u.z, u.w);
            aR = ffma2(make_float2(wR[k].x, wR[k].y), ulo, aR);
            aR = ffma2(make_float2(wR[k].z, wR[k].w), uhi, aR);
            aZ = ffma2(make_float2(wZ[k].x, wZ[k].y), ulo, aZ);
            aZ = ffma2(make_float2(wZ[k].z, wZ[k].w), uhi, aZ);
            aN = ffma2(make_float2(wN[k].x, wN[k].y), ulo, aN);
            aN = ffma2(make_float2(wN[k].z, wN[k].w), uhi, aN);
        }
        float dR = aR.x + aR.y, dZ = aZ.x + aZ.y, dN = aN.x + aN.y;

        if (isL0) {
            dR += __shfl_xor_sync(0xffffffffu, dR, 1);
            dZ += __shfl_xor_sync(0xffffffffu, dZ, 1);
            dN += __shfl_xor_sync(0xffffffffu, dN, 1);
            if (i < Tq && seg == 0) {
                float r = siga(gxR + dR + bR);
                float z = siga(gxZ + dZ + bZ);
                float n = tanha(fmaf(r, dN + bNh, gxN));   // gxN includes b_ih0
                float hn = (1.0f - z) * n + z * hprev;
                hprev = hn;
                hbuf[p ^ 1][j >> 5][j & 31] = hn;
            }
            gxR = nR; gxZ = nZ; gxN = nN;
        } else {
            // xor1: combine within side (segs {0,1} x-side, {2,3} h-side)
            dR += __shfl_xor_sync(0xffffffffu, dR, 1);
            dZ += __shfl_xor_sync(0xffffffffu, dZ, 1);
            dN += __shfl_xor_sync(0xffffffffu, dN, 1);
            // xor2: sum r/z across sides; exchange opposite side's n-dot
            float oR = __shfl_xor_sync(0xffffffffu, dR, 2);
            float oZ = __shfl_xor_sync(0xffffffffu, dZ, 2);
            float oN = __shfl_xor_sync(0xffffffffu, dN, 2);
            dR += oR; dZ += oZ;
            if (i > 0 && seg == 0) {
                float r = siga(dR + bR);
                float z = siga(dZ + bZ);
                float n = tanha(fmaf(r, oN + bNh, dN + bNi));  // dN=x-side, oN=h-side
                float hn = (1.0f - z) * n + z * hprev;
                hprev = hn;
                hbuf[p ^ 1][2 + (j >> 5)][j & 31] = hn;
            }
        }
        __syncthreads();   // publish h0^{i+1}, h1^{i} for next iteration
    }

    // ---- epilogue: h0 final in parity 0 q0/q1, h1 final q2/q3 (parity 1) ----
    if (write_hidden && tid < 2 * Hq) {
        if (tid < Hq)
            out[Bq * Oq + batch * Hq + tid] = hbuf[0][tid >> 5][tid & 31];
        else {
            int jj = tid - Hq;
            out[Bq * Oq + Bq * Hq + batch * Hq + jj] = hbuf[1][2 + (jj >> 5)][jj & 31];
        }
    }
    if (tid < Oq) {
        float acc = b_fc[tid];
        #pragma unroll
        for (int jj = 0; jj < Hq; ++jj)
            acc = fmaf(fmaxf(hbuf[1][2 + (jj >> 5)][jj & 31], 0.0f),
                       __ldg(&W_fc[tid * Hq + jj]), acc);
        out[batch * Oq + tid] = acc;
    }
}

// ---------------------------------------------------------------------------
extern "C" void kernel_launch(void* const* d_in, const int* in_sizes, int n_in,
                              void* d_out, int out_size) {
    const float* x     = (const float*)d_in[0];
    const float* h     = (const float*)d_in[1];
    const float* W_ih0 = (const float*)d_in[2];
    const float* W_hh0 = (const float*)d_in[3];
    const float* b_ih0 = (const float*)d_in[4];
    const float* b_hh0 = (const float*)d_in[5];
    const float* W_ih1 = (const float*)d_in[6];
    const float* W_hh1 = (const float*)d_in[7];
    const float* b_ih1 = (const float*)d_in[8];
    const float* b_hh1 = (const float*)d_in[9];
    const float* W_fc  = (const float*)d_in[10];
    const float* b_fc  = (const float*)d_in[11];
    float* out = (float*)d_out;

    gx0_kernel<<<Bq, 192>>>(x, W_ih0, b_ih0);

    int write_hidden = (out_size >= Bq * Oq + 2 * Bq * Hq) ? 1 : 0;
    rnn_kernel<<<Bq, 384>>>(h, W_hh0, b_hh0,
                            W_ih1, W_hh1, b_ih1, b_hh1,
                            W_fc, b_fc, out, write_hidden);
}